// round 13
// baseline (speedup 1.0000x reference)
#include <cuda_runtime.h>
#include <math.h>

#define B_ 16
#define HW 4096          // 64*64
#define CD 32
#define DIMX 512
#define NSCALES 14
#define NPIX (B_*HW)                 // 65536
#define OUT_ELEMS (B_*DIMX*HW)       // 33554432

#define INV_SQRT32 0.17677669529663687f
#define ACOEF 70.710678118654755f    // 4*100/sqrt(32); p = sigmoid(-ACOEF*z)

__device__ float g_r0[NPIX*CD];      // original projection (token-major)
__device__ float g_r [NPIX*CD];      // residual (ping A)
__device__ float g_part[4][NPIX*CD]; // split-K partials; g_part[0] doubles as ping B
__device__ float g_pool[94720];      // pooled sums, float pools scales 0..6
__device__ unsigned g_bits[82720];   // sign bitmaps, scales 7..12
__device__ float g_acc[NSCALES][34]; // [0..31]=sum p, [32]=sum H, [33]=sum commit

__constant__ int c_ph[13]   = {1,2,3,4,5,7,9,12,16,21,27,36,48};
__constant__ int c_poff[7]  = {0,512,2560,7168,15360,28160,53248};    // float pools s<7
__constant__ int c_boff[13] = {0,0,0,0,0,0,0, 0,2304,6400,13456,25120,45856}; // bitmaps s>=7
#define SLICED_POOL_FLOATS 94720

// ---------------------------------------------------------------- f32x2 helpers
__device__ __forceinline__ unsigned long long pk2(float x, float y) {
    unsigned long long r;
    asm("mov.b64 %0, {%1, %2};" : "=l"(r) : "f"(x), "f"(y));
    return r;
}
__device__ __forceinline__ unsigned long long fma2(unsigned long long a,
                                                   unsigned long long b,
                                                   unsigned long long c) {
    unsigned long long d;
    asm("fma.rn.f32x2 %0, %1, %2, %3;" : "=l"(d) : "l"(a), "l"(b), "l"(c));
    return d;
}
__device__ __forceinline__ void upk2(unsigned long long v, float& lo, float& hi) {
    asm("mov.b64 {%0, %1}, %2;" : "=f"(lo), "=f"(hi) : "l"(v));
}

// ---------------------------------------------------------------- init (every replay)
__global__ void init_kernel() {
    int t = blockIdx.x * blockDim.x + threadIdx.x;
    for (int i = t; i < SLICED_POOL_FLOATS; i += gridDim.x * blockDim.x)
        g_pool[i] = 0.f;
    if (t < NSCALES * 34) ((float*)g_acc)[t] = 0.f;
}

// ---------------------------------------------------------------- proj_in GEMM (split-K=4, 1 px/thread)
__global__ __launch_bounds__(256) void gemm_in_kernel(
        const float* __restrict__ x, const float* __restrict__ w_in) {
    __shared__ float s_w[128 * CD];
    int tid = threadIdx.x;
    int kc = blockIdx.x & 3;
    int pg = blockIdx.x >> 2;
    const float* wsrc = w_in + kc * 128 * CD;
    for (int i = tid; i < 128 * CD; i += 256) s_w[i] = wsrc[i];
    __syncthreads();

    int px = pg * 256 + tid;
    int b = px >> 12, pl = px & 4095;
    const float* xp = x + (size_t)b * (DIMX * HW) + (size_t)(kc * 128) * HW + pl;

    unsigned long long a[16];
#pragma unroll
    for (int i = 0; i < 16; i++) a[i] = 0ull;

#pragma unroll 4
    for (int c = 0; c < 128; c++) {
        float f = xp[(size_t)c * HW];
        unsigned long long X = pk2(f, f);
        const ulonglong2* row = (const ulonglong2*)(s_w + c * CD);
#pragma unroll
        for (int r = 0; r < 8; r++) {
            ulonglong2 w2 = row[r];
            a[2*r]   = fma2(X, w2.x, a[2*r]);
            a[2*r+1] = fma2(X, w2.y, a[2*r+1]);
        }
    }
    ulonglong2* o = (ulonglong2*)(g_part[kc] + (size_t)px * CD);
#pragma unroll
    for (int k = 0; k < 8; k++) {
        ulonglong2 v; v.x = a[2*k]; v.y = a[2*k+1];
        o[k] = v;
    }
}

// combine: r0 = r = ((p0+p1)+(p2+p3)) + bias
__global__ __launch_bounds__(256) void combine_kernel(const float* __restrict__ b_in) {
    int idx = blockIdx.x * 256 + threadIdx.x;
    float4 p0 = __ldg((const float4*)g_part[0] + idx);
    float4 p1 = __ldg((const float4*)g_part[1] + idx);
    float4 p2 = __ldg((const float4*)g_part[2] + idx);
    float4 p3 = __ldg((const float4*)g_part[3] + idx);
    float4 bi = __ldg((const float4*)b_in + (idx & 7));
    float4 v;
    v.x = (p0.x + p1.x) + (p2.x + p3.x) + bi.x;
    v.y = (p0.y + p1.y) + (p2.y + p3.y) + bi.y;
    v.z = (p0.z + p1.z) + (p2.z + p3.z) + bi.z;
    v.w = (p0.w + p1.w) + (p2.w + p3.w) + bi.w;
    ((float4*)g_r0)[idx] = v;
    ((float4*)g_r )[idx] = v;
}

// ---------------------------------------------------------------- per-token loss math (lane=d)
__device__ __forceinline__ void loss_token(float ir, float& pa, float& ha, float& ca) {
    float n2 = ir * ir;
#pragma unroll
    for (int o = 16; o > 0; o >>= 1) n2 += __shfl_xor_sync(~0u, n2, o);
    float z = ir / fmaxf(sqrtf(n2), 1e-12f);
    float p = 1.f / (1.f + expf(ACOEF * z));
    float H = -(p * logf(p + 1e-8f) + (1.f - p) * logf(1.f - p + 1e-8f));
    float qv = (z > 0.f) ? INV_SQRT32 : -INV_SQRT32;
    float dz = z - qv;
    pa += p; ha += H; ca += dz * dz;
}

// ---------------------------------------------------------------- pool, scales 0..6 (row x 16px chunks, atomic)
__global__ __launch_bounds__(256) void pool_small_kernel(int s, int S, int Sx) {
    int tid = threadIdx.x, lane = tid & 31;
    int ph = c_ph[s], np = ph * ph, ntok = B_ * np;
    int base = c_poff[s];
    int w = blockIdx.x * 8 + (tid >> 5);
    if (w >= ntok * S * Sx) return;
    int tok = w / (S * Sx);
    int r2 = w - tok * (S * Sx);
    int sy = r2 / Sx, sx = r2 - sy * Sx;
    int b = tok / np, ij = tok - b * np, i = ij / ph, j = ij - i * ph;
    int sh = (i * 64) / ph, eh = ((i + 1) * 64 + ph - 1) / ph;
    int y = sh + sy;
    if (y >= eh) return;
    int sw = (j * 64) / ph, ew = ((j + 1) * 64 + ph - 1) / ph;
    int xs = sw + sx * 16;
    if (xs >= ew) return;
    int xe = min(ew, xs + 16);
    const float* row = g_r + ((size_t)(b * HW + y * 64)) * CD + lane;

    float s0 = 0.f, s1 = 0.f, s2 = 0.f, s3 = 0.f;
    int x = xs;
    for (; x + 8 <= xe; x += 8) {
        float a0 = row[(size_t)(x+0) * CD];
        float a1 = row[(size_t)(x+1) * CD];
        float a2 = row[(size_t)(x+2) * CD];
        float a3 = row[(size_t)(x+3) * CD];
        float a4 = row[(size_t)(x+4) * CD];
        float a5 = row[(size_t)(x+5) * CD];
        float a6 = row[(size_t)(x+6) * CD];
        float a7 = row[(size_t)(x+7) * CD];
        s0 += a0 + a4;
        s1 += a1 + a5;
        s2 += a2 + a6;
        s3 += a3 + a7;
    }
    for (; x < xe; x++) s0 += row[(size_t)x * CD];
    float sum = (s0 + s1) + (s2 + s3);
    atomicAdd(&g_pool[base + tok * CD + lane], sum);
}

// ---------------------------------------------------------------- up, scales 0..5 (float pools, fused loss(s)); grid 2048
__global__ __launch_bounds__(256) void up_kernel(int s) {
    __shared__ int s_i0[64], s_i1[64];
    __shared__ float s_f[64];
    __shared__ float s_red[34];
    int tid = threadIdx.x, lane = tid & 31;
    int ph = c_ph[s], np = ph * ph;

    if (tid < 64) {
        float src = ((float)tid + 0.5f) * (float)ph * 0.015625f - 0.5f;
        src = fminf(fmaxf(src, 0.f), (float)(ph - 1));
        int i0 = (int)src;
        s_i0[tid] = i0;
        s_i1[tid] = min(i0 + 1, ph - 1);
        s_f[tid]  = src - (float)i0;
    }
    if (tid < 34) s_red[tid] = 0.f;
    __syncthreads();

    int gw = blockIdx.x * 8 + (tid >> 5);
    const float* pool = g_pool + c_poff[s];

    {   // loss(s): ntok <= 784 for s<=5
        int ntok = B_ * np;
        if (gw < ntok) {
            int tok = gw;
            int b = tok / np, ij = tok - b * np, i = ij / ph, j = ij - i * ph;
            int ah = ((i + 1) * 64 + ph - 1) / ph - (i * 64) / ph;
            int aw = ((j + 1) * 64 + ph - 1) / ph - (j * 64) / ph;
            float ir = pool[tok * CD + lane] / (float)(ah * aw);
            float pa = 0.f, ha = 0.f, ca = 0.f;
            loss_token(ir, pa, ha, ca);
#pragma unroll
            for (int o = 16; o > 0; o >>= 1) {
                ha += __shfl_xor_sync(~0u, ha, o);
                ca += __shfl_xor_sync(~0u, ca, o);
            }
            atomicAdd(&s_red[lane], pa);
            if (lane == 0) { atomicAdd(&s_red[32], ha); atomicAdd(&s_red[33], ca); }
        }
    }

    int sub = lane >> 3, q = lane & 7;
    int px = gw * 4 + sub;
    int b = px >> 12, h = (px >> 6) & 63, w = px & 63;
    int i0 = s_i0[h], i1 = s_i1[h]; float fh = s_f[h];
    int j0 = s_i0[w], j1 = s_i1[w]; float fw = s_f[w];
    int tb = b * np;
    float4 p00 = *(const float4*)(pool + (tb + i0 * ph + j0) * CD + 4 * q);
    float4 p01 = *(const float4*)(pool + (tb + i0 * ph + j1) * CD + 4 * q);
    float4 p10 = *(const float4*)(pool + (tb + i1 * ph + j0) * CD + 4 * q);
    float4 p11 = *(const float4*)(pool + (tb + i1 * ph + j1) * CD + 4 * q);
    const float* a00 = (const float*)&p00;
    const float* a01 = (const float*)&p01;
    const float* a10 = (const float*)&p10;
    const float* a11 = (const float*)&p11;
    float v[4];
#pragma unroll
    for (int k = 0; k < 4; k++) {
        float s00 = a00[k] > 0.f ? 1.f : -1.f;
        float s01 = a01[k] > 0.f ? 1.f : -1.f;
        float s10 = a10[k] > 0.f ? 1.f : -1.f;
        float s11 = a11[k] > 0.f ? 1.f : -1.f;
        float top = s00 + fw * (s01 - s00);
        float bot = s10 + fw * (s11 - s10);
        v[k] = INV_SQRT32 * (top + fh * (bot - top));
    }
    float4* rp = (float4*)(g_r + (size_t)px * CD + 4 * q);
    float4 rv = *rp;
    rv.x -= v[0]; rv.y -= v[1]; rv.z -= v[2]; rv.w -= v[3];
    *rp = rv;

    __syncthreads();
    if (tid < 34) atomicAdd(&g_acc[s][tid], s_red[tid]);
}

// ---------------------------------------------------------------- fused BLOCK-per-token, s=6..8
// block = one scale-(s+1) token; 128 thr = 4 warps share the region.
// up(s) on region px (ownership write), pooled sum via deterministic smem tree,
// bits(s+1) + loss(s+1); s==6 additionally loss(6) from pool6 floats.
__global__ __launch_bounds__(128) void fused_blk_kernel(int s, int flip) {
    __shared__ int s_i0[64], s_i1[64];
    __shared__ float s_f[64];
    __shared__ float s_part[4][32];
    int tid = threadIdx.x, lane = tid & 31, wid = tid >> 5;
    int sub = lane >> 3, q = lane & 7;
    int ph = c_ph[s], np = ph * ph;
    int phn = c_ph[s + 1], npn = phn * phn;
    const float* rsrc = flip ? g_part[0] : g_r;
    float*       rdst = flip ? g_r : g_part[0];
    const float* poolS = g_pool + c_poff[6];              // s==6 only
    const unsigned* bitsS = g_bits + c_boff[s];           // s>=7 only
    unsigned* bits_out = g_bits + c_boff[s + 1];

    if (tid < 64) {
        float src = ((float)tid + 0.5f) * (float)ph * 0.015625f - 0.5f;
        src = fminf(fmaxf(src, 0.f), (float)(ph - 1));
        int i0 = (int)src;
        s_i0[tid] = i0;
        s_i1[tid] = min(i0 + 1, ph - 1);
        s_f[tid]  = src - (float)i0;
    }
    __syncthreads();

    // optional loss(6): warp 1 of blocks < ntok(6)
    if (s == 6 && wid == 1) {
        int ntok6 = B_ * np;                               // 1296
        int tok = blockIdx.x;
        if (tok < ntok6) {
            int b = tok / np, ij = tok - b * np, i = ij / ph, j = ij - i * ph;
            int ah = ((i + 1) * 64 + ph - 1) / ph - (i * 64) / ph;
            int aw = ((j + 1) * 64 + ph - 1) / ph - (j * 64) / ph;
            float ir = poolS[tok * CD + lane] / (float)(ah * aw);
            float pa = 0.f, ha = 0.f, ca = 0.f;
            loss_token(ir, pa, ha, ca);
#pragma unroll
            for (int o = 16; o > 0; o >>= 1) {
                ha += __shfl_xor_sync(~0u, ha, o);
                ca += __shfl_xor_sync(~0u, ca, o);
            }
            atomicAdd(&g_acc[6][lane], pa);
            if (lane == 0) { atomicAdd(&g_acc[6][32], ha); atomicAdd(&g_acc[6][33], ca); }
        }
    }

    // token of THIS block at scale s+1
    int t = blockIdx.x;
    int b = t / npn, ij = t - b * npn, i = ij / phn, j = ij - i * phn;
    int sh = (i * 64) / phn, eh = ((i + 1) * 64 + phn - 1) / phn;
    int sw = (j * 64) / phn, ew = ((j + 1) * 64 + phn - 1) / phn;
    int sh2 = (i * 64 + phn - 1) / phn;     // owned partition start
    int sw2 = (j * 64 + phn - 1) / phn;
    int rh = eh - sh, rw = ew - sw;
    int npx = rh * rw;                      // <= 36
    int tb = b * np;

    float4 acc = make_float4(0.f, 0.f, 0.f, 0.f);
    int iters = (npx + 15) >> 4;            // 16 px per sweep (4 warps x 4 subs)
    for (int it = 0; it < iters; it++) {
        int rp2 = it * 16 + wid * 4 + sub;
        bool valid = rp2 < npx;
        int rpc = valid ? rp2 : 0;
        int dy = rpc / rw, dx = rpc - dy * rw;
        int h = sh + dy, w2 = sw + dx;
        int px = (b << 12) + (h << 6) + w2;

        int i0 = s_i0[h], i1 = s_i1[h]; float fh = s_f[h];
        int j0 = s_i0[w2], j1 = s_i1[w2]; float fw = s_f[w2];
        int t00 = tb + i0 * ph + j0, t01 = tb + i0 * ph + j1;
        int t10 = tb + i1 * ph + j0, t11 = tb + i1 * ph + j1;

        float v[4];
        if (s >= 7) {
            unsigned w00 = bitsS[t00], w01 = bitsS[t01];
            unsigned w10 = bitsS[t10], w11 = bitsS[t11];
#pragma unroll
            for (int k = 0; k < 4; k++) {
                int d = 4 * q + k;
                float s00 = ((w00 >> d) & 1u) ? 1.f : -1.f;
                float s01 = ((w01 >> d) & 1u) ? 1.f : -1.f;
                float s10 = ((w10 >> d) & 1u) ? 1.f : -1.f;
                float s11 = ((w11 >> d) & 1u) ? 1.f : -1.f;
                float top = s00 + fw * (s01 - s00);
                float bot = s10 + fw * (s11 - s10);
                v[k] = INV_SQRT32 * (top + fh * (bot - top));
            }
        } else {
            float4 p00 = *(const float4*)(poolS + t00 * CD + 4 * q);
            float4 p01 = *(const float4*)(poolS + t01 * CD + 4 * q);
            float4 p10 = *(const float4*)(poolS + t10 * CD + 4 * q);
            float4 p11 = *(const float4*)(poolS + t11 * CD + 4 * q);
            const float* a00 = (const float*)&p00;
            const float* a01 = (const float*)&p01;
            const float* a10 = (const float*)&p10;
            const float* a11 = (const float*)&p11;
#pragma unroll
            for (int k = 0; k < 4; k++) {
                float s00 = a00[k] > 0.f ? 1.f : -1.f;
                float s01 = a01[k] > 0.f ? 1.f : -1.f;
                float s10 = a10[k] > 0.f ? 1.f : -1.f;
                float s11 = a11[k] > 0.f ? 1.f : -1.f;
                float top = s00 + fw * (s01 - s00);
                float bot = s10 + fw * (s11 - s10);
                v[k] = INV_SQRT32 * (top + fh * (bot - top));
            }
        }

        float4 rv = *(const float4*)(rsrc + (size_t)px * CD + 4 * q);
        rv.x -= v[0]; rv.y -= v[1]; rv.z -= v[2]; rv.w -= v[3];
        if (valid && h >= sh2 && w2 >= sw2)
            *(float4*)(rdst + (size_t)px * CD + 4 * q) = rv;
        if (valid) {
            acc.x += rv.x; acc.y += rv.y; acc.z += rv.z; acc.w += rv.w;
        }
    }

    // deterministic: cross-sub tree within warp, then fixed warp order in smem
    acc.x += __shfl_xor_sync(~0u, acc.x, 8);  acc.x += __shfl_xor_sync(~0u, acc.x, 16);
    acc.y += __shfl_xor_sync(~0u, acc.y, 8);  acc.y += __shfl_xor_sync(~0u, acc.y, 16);
    acc.z += __shfl_xor_sync(~0u, acc.z, 8);  acc.z += __shfl_xor_sync(~0u, acc.z, 16);
    acc.w += __shfl_xor_sync(~0u, acc.w, 8);  acc.w += __shfl_xor_sync(~0u, acc.w, 16);
    if (sub == 0) {
        s_part[wid][4*q+0] = acc.x;
        s_part[wid][4*q+1] = acc.y;
        s_part[wid][4*q+2] = acc.z;
        s_part[wid][4*q+3] = acc.w;
    }
    __syncthreads();

    if (wid == 0) {
        float pooled = ((s_part[0][lane] + s_part[1][lane])
                      + (s_part[2][lane] + s_part[3][lane]));
        unsigned word = __ballot_sync(~0u, pooled > 0.f);
        if (lane == 0) bits_out[t] = word;
        float ir = pooled / (float)npx;
        float pa = 0.f, ha = 0.f, ca = 0.f;
        loss_token(ir, pa, ha, ca);
#pragma unroll
        for (int o = 16; o > 0; o >>= 1) {
            ha += __shfl_xor_sync(~0u, ha, o);
            ca += __shfl_xor_sync(~0u, ca, o);
        }
        atomicAdd(&g_acc[s + 1][lane], pa);
        if (lane == 0) { atomicAdd(&g_acc[s + 1][32], ha); atomicAdd(&g_acc[s + 1][33], ca); }
    }
}

// ---------------------------------------------------------------- fused WARP-per-token, s=9..11 (bits in, bits out)
__global__ __launch_bounds__(256) void fused_warp_kernel(int s, int flip) {
    __shared__ int s_i0[64], s_i1[64];
    __shared__ float s_f[64];
    __shared__ float s_red[34];
    int tid = threadIdx.x, lane = tid & 31;
    int ph = c_ph[s], np = ph * ph;
    int phn = c_ph[s + 1], npn = phn * phn;
    const float* rsrc = flip ? g_part[0] : g_r;
    float*       rdst = flip ? g_r : g_part[0];
    const unsigned* bitsS = g_bits + c_boff[s];
    unsigned* bits_out = g_bits + c_boff[s + 1];

    if (tid < 64) {
        float src = ((float)tid + 0.5f) * (float)ph * 0.015625f - 0.5f;
        src = fminf(fmaxf(src, 0.f), (float)(ph - 1));
        int i0 = (int)src;
        s_i0[tid] = i0;
        s_i1[tid] = min(i0 + 1, ph - 1);
        s_f[tid]  = src - (float)i0;
    }
    if (tid < 34) s_red[tid] = 0.f;
    __syncthreads();

    int gw = blockIdx.x * 8 + (tid >> 5);
    int sub = lane >> 3, q = lane & 7;
    int ntokn = B_ * npn;
    int t = gw;
    bool active = (t < ntokn);
    float4 acc = make_float4(0.f, 0.f, 0.f, 0.f);
    float inv_area = 1.f;

    if (active) {
        int b = t / npn, ij = t - b * npn, i = ij / phn, j = ij - i * phn;
        int sh = (i * 64) / phn, eh = ((i + 1) * 64 + phn - 1) / phn;
        int sw = (j * 64) / phn, ew = ((j + 1) * 64 + phn - 1) / phn;
        int sh2 = (i * 64 + phn - 1) / phn;
        int sw2 = (j * 64 + phn - 1) / phn;
        int rh = eh - sh, rw = ew - sw;
        int npx = rh * rw;                   // <= 25
        inv_area = 1.f / (float)npx;
        int iters = (npx + 3) >> 2;
        int tb = b * np;

        for (int it = 0; it < iters; it++) {
            int rp2 = it * 4 + sub;
            bool valid = rp2 < npx;
            int rpc = valid ? rp2 : 0;
            int dy = rpc / rw, dx = rpc - dy * rw;
            int h = sh + dy, w2 = sw + dx;
            int px = (b << 12) + (h << 6) + w2;

            int i0 = s_i0[h], i1 = s_i1[h]; float fh = s_f[h];
            int j0 = s_i0[w2], j1 = s_i1[w2]; float fw = s_f[w2];
            unsigned w00 = bitsS[tb + i0 * ph + j0], w01 = bitsS[tb + i0 * ph + j1];
            unsigned w10 = bitsS[tb + i1 * ph + j0], w11 = bitsS[tb + i1 * ph + j1];

            float v[4];
#pragma unroll
            for (int k = 0; k < 4; k++) {
                int d = 4 * q + k;
                float s00 = ((w00 >> d) & 1u) ? 1.f : -1.f;
                float s01 = ((w01 >> d) & 1u) ? 1.f : -1.f;
                float s10 = ((w10 >> d) & 1u) ? 1.f : -1.f;
                float s11 = ((w11 >> d) & 1u) ? 1.f : -1.f;
                float top = s00 + fw * (s01 - s00);
                float bot = s10 + fw * (s11 - s10);
                v[k] = INV_SQRT32 * (top + fh * (bot - top));
            }

            float4 rv = *(const float4*)(rsrc + (size_t)px * CD + 4 * q);
            rv.x -= v[0]; rv.y -= v[1]; rv.z -= v[2]; rv.w -= v[3];
            if (valid && h >= sh2 && w2 >= sw2)
                *(float4*)(rdst + (size_t)px * CD + 4 * q) = rv;
            if (valid) {
                acc.x += rv.x; acc.y += rv.y; acc.z += rv.z; acc.w += rv.w;
            }
        }
    }

    acc.x += __shfl_xor_sync(~0u, acc.x, 8);  acc.x += __shfl_xor_sync(~0u, acc.x, 16);
    acc.y += __shfl_xor_sync(~0u, acc.y, 8);  acc.y += __shfl_xor_sync(~0u, acc.y, 16);
    acc.z += __shfl_xor_sync(~0u, acc.z, 8);  acc.z += __shfl_xor_sync(~0u, acc.z, 16);
    acc.w += __shfl_xor_sync(~0u, acc.w, 8);  acc.w += __shfl_xor_sync(~0u, acc.w, 16);

    unsigned nib = (acc.x > 0.f ? 1u : 0u) | (acc.y > 0.f ? 2u : 0u)
                 | (acc.z > 0.f ? 4u : 0u) | (acc.w > 0.f ? 8u : 0u);
    unsigned word = nib << (4 * q);
    word |= __shfl_xor_sync(~0u, word, 1);
    word |= __shfl_xor_sync(~0u, word, 2);
    word |= __shfl_xor_sync(~0u, word, 4);
    if (active && lane == 0) bits_out[t] = word;

    {   // loss(s+1)
        float irx = acc.x * inv_area, iry = acc.y * inv_area;
        float irz = acc.z * inv_area, irw = acc.w * inv_area;
        float n2 = irx*irx + iry*iry + irz*irz + irw*irw;
        n2 += __shfl_xor_sync(~0u, n2, 1);
        n2 += __shfl_xor_sync(~0u, n2, 2);
        n2 += __shfl_xor_sync(~0u, n2, 4);
        float inv = 1.f / fmaxf(sqrtf(n2), 1e-12f);
        float ir4[4] = {irx, iry, irz, irw};
        float pv[4], ha = 0.f, ca = 0.f;
#pragma unroll
        for (int k = 0; k < 4; k++) {
            float z = ir4[k] * inv;
            float p = 1.f / (1.f + expf(ACOEF * z));
            ha += -(p * logf(p + 1e-8f) + (1.f - p) * logf(1.f - p + 1e-8f));
            float qv = (z > 0.f) ? INV_SQRT32 : -INV_SQRT32;
            float dz = z - qv;
            ca += dz * dz;
            pv[k] = p;
        }
        ha += __shfl_xor_sync(~0u, ha, 1);
        ha += __shfl_xor_sync(~0u, ha, 2);
        ha += __shfl_xor_sync(~0u, ha, 4);
        ca += __shfl_xor_sync(~0u, ca, 1);
        ca += __shfl_xor_sync(~0u, ca, 2);
        ca += __shfl_xor_sync(~0u, ca, 4);
        if (active && sub == 0) {
            atomicAdd(&s_red[4*q+0], pv[0]);
            atomicAdd(&s_red[4*q+1], pv[1]);
            atomicAdd(&s_red[4*q+2], pv[2]);
            atomicAdd(&s_red[4*q+3], pv[3]);
            if (q == 0) { atomicAdd(&s_red[32], ha); atomicAdd(&s_red[33], ca); }
        }
    }

    __syncthreads();
    if (tid < 34) atomicAdd(&g_acc[s + 1][tid], s_red[tid]);
}

// ---------------------------------------------------------------- up(12) + fused loss13; in-place on g_r (grid 2048)
__global__ __launch_bounds__(256) void up12_kernel() {
    __shared__ int s_i0[64], s_i1[64];
    __shared__ float s_f[64];
    __shared__ float s_13[34];
    int tid = threadIdx.x, lane = tid & 31;
    const int ph = 48, np = 48 * 48;

    if (tid < 64) {
        float src = ((float)tid + 0.5f) * 48.f * 0.015625f - 0.5f;
        src = fminf(fmaxf(src, 0.f), 47.f);
        int i0 = (int)src;
        s_i0[tid] = i0;
        s_i1[tid] = min(i0 + 1, 47);
        s_f[tid]  = src - (float)i0;
    }
    if (tid < 34) s_13[tid] = 0.f;
    __syncthreads();

    int gw = blockIdx.x * 8 + (tid >> 5);
    int sub = lane >> 3, q = lane & 7;
    int px = gw * 4 + sub;
    int b = px >> 12, h = (px >> 6) & 63, w = px & 63;
    int i0 = s_i0[h], i1 = s_i1[h]; float fh = s_f[h];
    int j0 = s_i0[w], j1 = s_i1[w]; float fw = s_f[w];
    int tb = b * np;
    const unsigned* bits = g_bits + 45856;
    unsigned w00 = bits[tb + i0 * ph + j0], w01 = bits[tb + i0 * ph + j1];
    unsigned w10 = bits[tb + i1 * ph + j0], w11 = bits[tb + i1 * ph + j1];

    float4* rp = (float4*)(g_r + (size_t)px * CD + 4 * q);
    float4 rv = *rp;
    float* rvp = (float*)&rv;
#pragma unroll
    for (int k = 0; k < 4; k++) {
        int d = 4 * q + k;
        float s00 = ((w00 >> d) & 1u) ? 1.f : -1.f;
        float s01 = ((w01 >> d) & 1u) ? 1.f : -1.f;
        float s10 = ((w10 >> d) & 1u) ? 1.f : -1.f;
        float s11 = ((w11 >> d) & 1u) ? 1.f : -1.f;
        float top = s00 + fw * (s01 - s00);
        float bot = s10 + fw * (s11 - s10);
        rvp[k] -= INV_SQRT32 * (top + fh * (bot - top));
    }
    *rp = rv;

    float n2 = rv.x*rv.x + rv.y*rv.y + rv.z*rv.z + rv.w*rv.w;
    n2 += __shfl_xor_sync(~0u, n2, 1);
    n2 += __shfl_xor_sync(~0u, n2, 2);
    n2 += __shfl_xor_sync(~0u, n2, 4);
    float inv = 1.f / fmaxf(sqrtf(n2), 1e-12f);
    float pv[4], ha = 0.f, ca = 0.f;
#pragma unroll
    for (int k = 0; k < 4; k++) {
        float z = rvp[k] * inv;
        float p = 1.f / (1.f + expf(ACOEF * z));
        ha += -(p * logf(p + 1e-8f) + (1.f - p) * logf(1.f - p + 1e-8f));
        float qv = (z > 0.f) ? INV_SQRT32 : -INV_SQRT32;
        float dz = z - qv;
        ca += dz * dz;
        pv[k] = p;
    }
    atomicAdd(&s_13[4*q+0], pv[0]);
    atomicAdd(&s_13[4*q+1], pv[1]);
    atomicAdd(&s_13[4*q+2], pv[2]);
    atomicAdd(&s_13[4*q+3], pv[3]);
#pragma unroll
    for (int o = 16; o > 0; o >>= 1) {
        ha += __shfl_xor_sync(~0u, ha, o);
        ca += __shfl_xor_sync(~0u, ca, o);
    }
    if (lane == 0) { atomicAdd(&s_13[32], ha); atomicAdd(&s_13[33], ca); }

    __syncthreads();
    if (tid < 34) atomicAdd(&g_acc[13][tid], s_13[tid]);
}

// ---------------------------------------------------------------- finalize losses
__global__ void finalize_kernel(float* __restrict__ loss_out) {
    int s = threadIdx.x >> 5;
    int lane = threadIdx.x & 31;
    if (s >= NSCALES) return;
    int ph = (s < 13) ? c_ph[s] : 64;
    float n = (float)(B_ * ph * ph);
    float ap = g_acc[s][lane] / n;
    float H = -(ap * logf(ap + 1e-8f) + (1.f - ap) * logf(1.f - ap + 1e-8f));
#pragma unroll
    for (int o = 16; o > 0; o >>= 1) H += __shfl_xor_sync(~0u, H, o);
    if (lane == 0) {
        float ps = g_acc[s][32] / n;
        float cm = g_acc[s][33] / (n * 32.f);
        loss_out[s] = (ps - H) * (0.1f / 100.f) + 0.25f * cm;
    }
}

// ---------------------------------------------------------------- proj_out GEMM (split-N=4, 1 px/thread)
__global__ __launch_bounds__(256) void gemm_out_kernel(
        const float* __restrict__ w_out,
        const float* __restrict__ b_out,
        float* __restrict__ out) {
    __shared__ float s_wt[128 * 36];
    __shared__ float s_b[128];
    int tid = threadIdx.x;
    int kc = blockIdx.x & 3;
    int pg = blockIdx.x >> 2;
    int c0 = kc * 128;
    for (int i = tid; i < 128 * CD; i += 256) {
        int d = i >> 7, c = i & 127;
        s_wt[c * 36 + d] = w_out[d * DIMX + c0 + c];
    }
    if (tid < 128) s_b[tid] = b_out[c0 + tid];
    __syncthreads();

    int px = pg * 256 + tid;
    int b = px >> 12, pl = px & 4095;
    size_t o = (size_t)px * CD;

    unsigned long long Q[16];
#pragma unroll
    for (int k = 0; k < 8; k++) {
        float4 a = __ldg((const float4*)(g_r0 + o) + k);
        float4 r = ((const float4*)(g_r + o))[k];
        float qx = (r.x > 0.f) ? INV_SQRT32 : -INV_SQRT32;
        float qy = (r.y > 0.f) ? INV_SQRT32 : -INV_SQRT32;
        float qz = (r.z > 0.f) ? INV_SQRT32 : -INV_SQRT32;
        float qw = (r.w > 0.f) ? INV_SQRT32 : -INV_SQRT32;
        Q[2*k]   = pk2(a.x - r.x + qx, a.y - r.y + qy);
        Q[2*k+1] = pk2(a.z - r.z + qz, a.w - r.w + qw);
    }

    float* op = out + (size_t)b * (DIMX * HW) + (size_t)c0 * HW + pl;
#pragma unroll 2
    for (int c = 0; c < 128; c++) {
        const ulonglong2* wrow = (const ulonglong2*)(s_wt + c * 36);
        unsigned long long ae = 0, ao = 0;
#pragma unroll
        for (int r = 0; r < 8; r++) {
            ulonglong2 W = wrow[r];
            ae = fma2(Q[2*r],   W.x, ae);
            ao = fma2(Q[2*r+1], W.y, ao);
        }
        float lo, hi, sum;
        upk2(ae, lo, hi); sum = lo + hi;
        upk2(ao, lo, hi); sum += lo + hi;
        op[(size_t)c * HW] = sum + s_b[c];
    }
}

// ---------------------------------------------------------------- launch
extern "C" void kernel_launch(void* const* d_in, const int* in_sizes, int n_in,
                              void* d_out, int out_size) {
    const float* x     = (const float*)d_in[0];
    const float* w_in  = (const float*)d_in[1];
    const float* b_in  = (const float*)d_in[2];
    const float* w_out = (const float*)d_in[3];
    const float* b_out = (const float*)d_in[4];
    float* out = (float*)d_out;

    static const int sched[13] = {1,2,3,4,5,7,9,12,16,21,27,36,48};
    static const int SxT[7]    = {4,2,2,1,1,1,1};

    init_kernel<<<370, 256>>>();
    gemm_in_kernel<<<1024, 256>>>(x, w_in);
    combine_kernel<<<2048, 256>>>(b_in);

    // s = 0..5: atomic float pool + pixel-parallel up (in-place on g_r)
    for (int s = 0; s < 6; s++) {
        int ph = sched[s];
        int ntok = B_ * ph * ph;
        int S = 64 / ph + 2;
        int Sx = SxT[s];
        int work = ntok * S * Sx;
        pool_small_kernel<<<(work + 7) / 8, 256>>>(s, S, Sx);
        up_kernel<<<2048, 256>>>(s);
    }
    // pool(6) floats
    {
        int ph = 9, ntok = B_ * ph * ph;
        int S = 64 / ph + 2;
        pool_small_kernel<<<(ntok * S + 7) / 8, 256>>>(6, S, 1);
    }
    // fused chain: ping-pong g_r <-> g_part[0]; ends in g_r
    fused_blk_kernel<<<B_ * 12 * 12, 128>>>(6, 0);    // r -> B ; bits7, loss6, loss7
    fused_blk_kernel<<<B_ * 16 * 16, 128>>>(7, 1);    // B -> r ; bits8, loss8
    fused_blk_kernel<<<B_ * 21 * 21, 128>>>(8, 0);    // r -> B ; bits9, loss9
    fused_warp_kernel<<<(B_ * 27 * 27 + 7) / 8, 256>>>(9, 1);    // B -> r ; bits10, loss10
    fused_warp_kernel<<<(B_ * 36 * 36 + 7) / 8, 256>>>(10, 0);   // r -> B ; bits11, loss11
    fused_warp_kernel<<<(B_ * 48 * 48 + 7) / 8, 256>>>(11, 1);   // B -> r ; bits12, loss12
    up12_kernel<<<2048, 256>>>();

    if (out_size >= OUT_ELEMS + NSCALES)
        finalize_kernel<<<1, NSCALES * 32>>>(out + OUT_ELEMS);
    gemm_out_kernel<<<1024, 256>>>(w_out, b_out, out);
}

// round 14
// speedup vs baseline: 1.1844x; 1.1844x over previous
#include <cuda_runtime.h>
#include <math.h>

#define B_ 16
#define HW 4096          // 64*64
#define CD 32
#define DIMX 512
#define NSCALES 14
#define NPIX (B_*HW)                 // 65536
#define OUT_ELEMS (B_*DIMX*HW)       // 33554432

#define INV_SQRT32 0.17677669529663687f
#define ACOEF 70.710678118654755f    // 4*100/sqrt(32); p = sigmoid(-ACOEF*z)

__device__ float g_r0[NPIX*CD];      // original projection (token-major)
__device__ float g_r [NPIX*CD];      // residual
__device__ float g_part[4][NPIX*CD]; // split-K partials for proj_in
__device__ float g_pool[94720];      // pooled sums, sliced scales 0..6 only
__device__ unsigned g_bits[82720];   // sign bitmaps, scales 7..12
__device__ float g_acc[NSCALES][34]; // [0..31]=sum p, [32]=sum H, [33]=sum commit

__constant__ int c_ph[13]   = {1,2,3,4,5,7,9,12,16,21,27,36,48};
__constant__ int c_poff[7]  = {0,512,2560,7168,15360,28160,53248};    // float pools s<7
__constant__ int c_boff[13] = {0,0,0,0,0,0,0, 0,2304,6400,13456,25120,45856}; // bitmaps s>=7
#define SLICED_POOL_FLOATS 94720

// ---------------------------------------------------------------- f32x2 helpers
__device__ __forceinline__ unsigned long long pk2(float x, float y) {
    unsigned long long r;
    asm("mov.b64 %0, {%1, %2};" : "=l"(r) : "f"(x), "f"(y));
    return r;
}
__device__ __forceinline__ unsigned long long fma2(unsigned long long a,
                                                   unsigned long long b,
                                                   unsigned long long c) {
    unsigned long long d;
    asm("fma.rn.f32x2 %0, %1, %2, %3;" : "=l"(d) : "l"(a), "l"(b), "l"(c));
    return d;
}
__device__ __forceinline__ void upk2(unsigned long long v, float& lo, float& hi) {
    asm("mov.b64 {%0, %1}, %2;" : "=f"(lo), "=f"(hi) : "l"(v));
}

// ---------------------------------------------------------------- proj_in GEMM (split-K=4, 1 px/thread)
__global__ __launch_bounds__(256) void gemm_in_kernel(
        const float* __restrict__ x, const float* __restrict__ w_in) {
    __shared__ float s_w[128 * CD];
    int tid = threadIdx.x;
    int kc = blockIdx.x & 3;
    int pg = blockIdx.x >> 2;
    const float* wsrc = w_in + kc * 128 * CD;
    for (int i = tid; i < 128 * CD; i += 256) s_w[i] = wsrc[i];
    __syncthreads();

    int px = pg * 256 + tid;
    int b = px >> 12, pl = px & 4095;
    const float* xp = x + (size_t)b * (DIMX * HW) + (size_t)(kc * 128) * HW + pl;

    unsigned long long a[16];
#pragma unroll
    for (int i = 0; i < 16; i++) a[i] = 0ull;

#pragma unroll 4
    for (int c = 0; c < 128; c++) {
        float f = xp[(size_t)c * HW];
        unsigned long long X = pk2(f, f);
        const ulonglong2* row = (const ulonglong2*)(s_w + c * CD);
#pragma unroll
        for (int r = 0; r < 8; r++) {
            ulonglong2 w2 = row[r];
            a[2*r]   = fma2(X, w2.x, a[2*r]);
            a[2*r+1] = fma2(X, w2.y, a[2*r+1]);
        }
    }
    ulonglong2* o = (ulonglong2*)(g_part[kc] + (size_t)px * CD);
#pragma unroll
    for (int k = 0; k < 8; k++) {
        ulonglong2 v; v.x = a[2*k]; v.y = a[2*k+1];
        o[k] = v;
    }
}

// combine: r0 = r = ((p0+p1)+(p2+p3)) + bias ; also zeroes pools + acc (runs before any consumer)
__global__ __launch_bounds__(256) void combine_kernel(const float* __restrict__ b_in) {
    int idx = blockIdx.x * 256 + threadIdx.x;   // 524288 threads, float4 index space
    float4 p0 = __ldg((const float4*)g_part[0] + idx);
    float4 p1 = __ldg((const float4*)g_part[1] + idx);
    float4 p2 = __ldg((const float4*)g_part[2] + idx);
    float4 p3 = __ldg((const float4*)g_part[3] + idx);
    float4 bi = __ldg((const float4*)b_in + (idx & 7));
    float4 v;
    v.x = (p0.x + p1.x) + (p2.x + p3.x) + bi.x;
    v.y = (p0.y + p1.y) + (p2.y + p3.y) + bi.y;
    v.z = (p0.z + p1.z) + (p2.z + p3.z) + bi.z;
    v.w = (p0.w + p1.w) + (p2.w + p3.w) + bi.w;
    ((float4*)g_r0)[idx] = v;
    ((float4*)g_r )[idx] = v;

    if (idx < SLICED_POOL_FLOATS) g_pool[idx] = 0.f;
    if (idx < NSCALES * 34) ((float*)g_acc)[idx] = 0.f;
}

// ---------------------------------------------------------------- per-token loss math (lane=d)
__device__ __forceinline__ void loss_token(float ir, float& pa, float& ha, float& ca) {
    float n2 = ir * ir;
#pragma unroll
    for (int o = 16; o > 0; o >>= 1) n2 += __shfl_xor_sync(~0u, n2, o);
    float z = ir / fmaxf(sqrtf(n2), 1e-12f);
    float p = 1.f / (1.f + expf(ACOEF * z));
    float H = -(p * logf(p + 1e-8f) + (1.f - p) * logf(1.f - p + 1e-8f));
    float qv = (z > 0.f) ? INV_SQRT32 : -INV_SQRT32;
    float dz = z - qv;
    pa += p; ha += H; ca += dz * dz;
}

// ---------------------------------------------------------------- pool, big scales (warp/token, fused loss, sign bitmap out)
__global__ __launch_bounds__(256) void pool_big_kernel(int s) {
    __shared__ float s_red[34];
    int tid = threadIdx.x, lane = tid & 31;
    if (tid < 34) s_red[tid] = 0.f;
    __syncthreads();

    int ph = c_ph[s], np = ph * ph, ntok = B_ * np;
    unsigned* bits = g_bits + c_boff[s];
    int gw = blockIdx.x * 8 + (tid >> 5);
    int nw = gridDim.x * 8;

    float pa = 0.f, ha = 0.f, ca = 0.f;
    for (int tok = gw; tok < ntok; tok += nw) {
        int b = tok / np, ij = tok - b * np, i = ij / ph, j = ij - i * ph;
        int sh = (i * 64) / ph, eh = ((i + 1) * 64 + ph - 1) / ph;
        int sw = (j * 64) / ph, ew = ((j + 1) * 64 + ph - 1) / ph;
        const float* rb = g_r + ((size_t)(b * HW)) * CD + lane;
        float sum = 0.f;
        for (int y = sh; y < eh; y++) {
            const float* row = rb + (size_t)(y * 64) * CD;
#pragma unroll 2
            for (int x = sw; x < ew; x++) sum += row[(size_t)x * CD];
        }
        unsigned word = __ballot_sync(~0u, sum > 0.f);
        if (lane == 0) bits[tok] = word;
        loss_token(sum / (float)((eh - sh) * (ew - sw)), pa, ha, ca);
    }
#pragma unroll
    for (int o = 16; o > 0; o >>= 1) {
        ha += __shfl_xor_sync(~0u, ha, o);
        ca += __shfl_xor_sync(~0u, ca, o);
    }
    atomicAdd(&s_red[lane], pa);
    if (lane == 0) { atomicAdd(&s_red[32], ha); atomicAdd(&s_red[33], ca); }
    __syncthreads();
    if (tid < 34) atomicAdd(&g_acc[s][tid], s_red[tid]);
}

// ---------------------------------------------------------------- pool, small scales (row x 16px chunks, atomic, deep MLP)
__global__ __launch_bounds__(256) void pool_small_kernel(int s, int S, int Sx) {
    int tid = threadIdx.x, lane = tid & 31;
    int ph = c_ph[s], np = ph * ph, ntok = B_ * np;
    int base = c_poff[s];
    int w = blockIdx.x * 8 + (tid >> 5);
    if (w >= ntok * S * Sx) return;
    int tok = w / (S * Sx);
    int r2 = w - tok * (S * Sx);
    int sy = r2 / Sx, sx = r2 - sy * Sx;
    int b = tok / np, ij = tok - b * np, i = ij / ph, j = ij - i * ph;
    int sh = (i * 64) / ph, eh = ((i + 1) * 64 + ph - 1) / ph;
    int y = sh + sy;
    if (y >= eh) return;
    int sw = (j * 64) / ph, ew = ((j + 1) * 64 + ph - 1) / ph;
    int xs = sw + sx * 16;
    if (xs >= ew) return;
    int xe = min(ew, xs + 16);
    const float* row = g_r + ((size_t)(b * HW + y * 64)) * CD + lane;

    float s0 = 0.f, s1 = 0.f, s2 = 0.f, s3 = 0.f;
    int x = xs;
    for (; x + 8 <= xe; x += 8) {
        float a0 = row[(size_t)(x+0) * CD];
        float a1 = row[(size_t)(x+1) * CD];
        float a2 = row[(size_t)(x+2) * CD];
        float a3 = row[(size_t)(x+3) * CD];
        float a4 = row[(size_t)(x+4) * CD];
        float a5 = row[(size_t)(x+5) * CD];
        float a6 = row[(size_t)(x+6) * CD];
        float a7 = row[(size_t)(x+7) * CD];
        s0 += a0 + a4;
        s1 += a1 + a5;
        s2 += a2 + a6;
        s3 += a3 + a7;
    }
    for (; x < xe; x++) s0 += row[(size_t)x * CD];
    float sum = (s0 + s1) + (s2 + s3);
    atomicAdd(&g_pool[base + tok * CD + lane], sum);
}

// ---------------------------------------------------------------- up: r -= bilerp(sign); 8 px/warp (2 px/thread);
// fused loss for sliced scales. grid MUST be 1024 blocks: 1024*8 warps * 8 px = 65536
__global__ __launch_bounds__(256) void up_kernel(int s, int sliced) {
    __shared__ int s_i0[64], s_i1[64];
    __shared__ float s_f[64];
    __shared__ float s_red[34];
    int tid = threadIdx.x, lane = tid & 31;
    int ph = c_ph[s], np = ph * ph;

    if (tid < 64) {
        float src = ((float)tid + 0.5f) * (float)ph * 0.015625f - 0.5f;
        src = fminf(fmaxf(src, 0.f), (float)(ph - 1));
        int i0 = (int)src;
        s_i0[tid] = i0;
        s_i1[tid] = min(i0 + 1, ph - 1);
        s_f[tid]  = src - (float)i0;
    }
    if (tid < 34) s_red[tid] = 0.f;
    __syncthreads();

    int gw = blockIdx.x * 8 + (tid >> 5);          // 8192 warps total

    if (sliced) {
        int ntok = B_ * np;                        // <= 1296 for s<7
        if (gw < ntok) {
            const float* pool = g_pool + c_poff[s];
            int tok = gw;
            int b = tok / np, ij = tok - b * np, i = ij / ph, j = ij - i * ph;
            int ah = ((i + 1) * 64 + ph - 1) / ph - (i * 64) / ph;
            int aw = ((j + 1) * 64 + ph - 1) / ph - (j * 64) / ph;
            float ir = pool[tok * CD + lane] / (float)(ah * aw);
            float pa = 0.f, ha = 0.f, ca = 0.f;
            loss_token(ir, pa, ha, ca);
#pragma unroll
            for (int o = 16; o > 0; o >>= 1) {
                ha += __shfl_xor_sync(~0u, ha, o);
                ca += __shfl_xor_sync(~0u, ca, o);
            }
            atomicAdd(&s_red[lane], pa);
            if (lane == 0) { atomicAdd(&s_red[32], ha); atomicAdd(&s_red[33], ca); }
        }
    }

    // pixel work: lane = sub(2b)*8 + q(3b); thread handles px = gw*8+sub and +4
    int sub = lane >> 3, q = lane & 7;
    int base = gw * 8;
#pragma unroll
    for (int half = 0; half < 2; half++) {
        int px = base + sub + half * 4;
        int b = px >> 12, h = (px >> 6) & 63, w = px & 63;
        int i0 = s_i0[h], i1 = s_i1[h]; float fh = s_f[h];
        int j0 = s_i0[w], j1 = s_i1[w]; float fw = s_f[w];
        int tb = b * np;
        int t00 = tb + i0 * ph + j0, t01 = tb + i0 * ph + j1;
        int t10 = tb + i1 * ph + j0, t11 = tb + i1 * ph + j1;

        float v[4];
        if (s >= 7) {
            const unsigned* bits = g_bits + c_boff[s];
            unsigned w00 = bits[t00], w01 = bits[t01];
            unsigned w10 = bits[t10], w11 = bits[t11];
#pragma unroll
            for (int k = 0; k < 4; k++) {
                int d = 4 * q + k;
                float s00 = ((w00 >> d) & 1u) ? 1.f : -1.f;
                float s01 = ((w01 >> d) & 1u) ? 1.f : -1.f;
                float s10 = ((w10 >> d) & 1u) ? 1.f : -1.f;
                float s11 = ((w11 >> d) & 1u) ? 1.f : -1.f;
                float top = s00 + fw * (s01 - s00);
                float bot = s10 + fw * (s11 - s10);
                v[k] = INV_SQRT32 * (top + fh * (bot - top));
            }
        } else {
            const float* pool = g_pool + c_poff[s];
            float4 p00 = *(const float4*)(pool + t00 * CD + 4 * q);
            float4 p01 = *(const float4*)(pool + t01 * CD + 4 * q);
            float4 p10 = *(const float4*)(pool + t10 * CD + 4 * q);
            float4 p11 = *(const float4*)(pool + t11 * CD + 4 * q);
            const float* a00 = (const float*)&p00;
            const float* a01 = (const float*)&p01;
            const float* a10 = (const float*)&p10;
            const float* a11 = (const float*)&p11;
#pragma unroll
            for (int k = 0; k < 4; k++) {
                float s00 = a00[k] > 0.f ? 1.f : -1.f;
                float s01 = a01[k] > 0.f ? 1.f : -1.f;
                float s10 = a10[k] > 0.f ? 1.f : -1.f;
                float s11 = a11[k] > 0.f ? 1.f : -1.f;
                float top = s00 + fw * (s01 - s00);
                float bot = s10 + fw * (s11 - s10);
                v[k] = INV_SQRT32 * (top + fh * (bot - top));
            }
        }

        float4* rp = (float4*)(g_r + (size_t)px * CD + 4 * q);
        float4 rv = *rp;
        rv.x -= v[0]; rv.y -= v[1]; rv.z -= v[2]; rv.w -= v[3];
        *rp = rv;
    }

    if (sliced) {
        __syncthreads();
        if (tid < 34) atomicAdd(&g_acc[s][tid], s_red[tid]);
    }
}

// ---------------------------------------------------------------- up(12) + fused loss13; in-place on g_r (grid 2048)
__global__ __launch_bounds__(256) void up12_kernel() {
    __shared__ int s_i0[64], s_i1[64];
    __shared__ float s_f[64];
    __shared__ float s_13[34];
    int tid = threadIdx.x, lane = tid & 31;
    const int ph = 48, np = 48 * 48;

    if (tid < 64) {
        float src = ((float)tid + 0.5f) * 48.f * 0.015625f - 0.5f;
        src = fminf(fmaxf(src, 0.f), 47.f);
        int i0 = (int)src;
        s_i0[tid] = i0;
        s_i1[tid] = min(i0 + 1, 47);
        s_f[tid]  = src - (float)i0;
    }
    if (tid < 34) s_13[tid] = 0.f;
    __syncthreads();

    int gw = blockIdx.x * 8 + (tid >> 5);
    int sub = lane >> 3, q = lane & 7;
    int px = gw * 4 + sub;
    int b = px >> 12, h = (px >> 6) & 63, w = px & 63;
    int i0 = s_i0[h], i1 = s_i1[h]; float fh = s_f[h];
    int j0 = s_i0[w], j1 = s_i1[w]; float fw = s_f[w];
    int tb = b * np;
    const unsigned* bits = g_bits + 45856;   // scale-12 bitmap
    unsigned w00 = bits[tb + i0 * ph + j0], w01 = bits[tb + i0 * ph + j1];
    unsigned w10 = bits[tb + i1 * ph + j0], w11 = bits[tb + i1 * ph + j1];

    float4* rp = (float4*)(g_r + (size_t)px * CD + 4 * q);
    float4 rv = *rp;
    float* rvp = (float*)&rv;
#pragma unroll
    for (int k = 0; k < 4; k++) {
        int d = 4 * q + k;
        float s00 = ((w00 >> d) & 1u) ? 1.f : -1.f;
        float s01 = ((w01 >> d) & 1u) ? 1.f : -1.f;
        float s10 = ((w10 >> d) & 1u) ? 1.f : -1.f;
        float s11 = ((w11 >> d) & 1u) ? 1.f : -1.f;
        float top = s00 + fw * (s01 - s00);
        float bot = s10 + fw * (s11 - s10);
        rvp[k] -= INV_SQRT32 * (top + fh * (bot - top));
    }
    *rp = rv;

    // fused loss13 (identity tokens = pixels) on new residuals
    float n2 = rv.x*rv.x + rv.y*rv.y + rv.z*rv.z + rv.w*rv.w;
    n2 += __shfl_xor_sync(~0u, n2, 1);
    n2 += __shfl_xor_sync(~0u, n2, 2);
    n2 += __shfl_xor_sync(~0u, n2, 4);
    float inv = 1.f / fmaxf(sqrtf(n2), 1e-12f);
    float pv[4], ha = 0.f, ca = 0.f;
#pragma unroll
    for (int k = 0; k < 4; k++) {
        float z = rvp[k] * inv;
        float p = 1.f / (1.f + expf(ACOEF * z));
        ha += -(p * logf(p + 1e-8f) + (1.f - p) * logf(1.f - p + 1e-8f));
        float qv = (z > 0.f) ? INV_SQRT32 : -INV_SQRT32;
        float dz = z - qv;
        ca += dz * dz;
        pv[k] = p;
    }
    atomicAdd(&s_13[4*q+0], pv[0]);
    atomicAdd(&s_13[4*q+1], pv[1]);
    atomicAdd(&s_13[4*q+2], pv[2]);
    atomicAdd(&s_13[4*q+3], pv[3]);
#pragma unroll
    for (int o = 16; o > 0; o >>= 1) {
        ha += __shfl_xor_sync(~0u, ha, o);
        ca += __shfl_xor_sync(~0u, ca, o);
    }
    if (lane == 0) { atomicAdd(&s_13[32], ha); atomicAdd(&s_13[33], ca); }

    __syncthreads();
    if (tid < 34) atomicAdd(&g_acc[13][tid], s_13[tid]);
}

// ---------------------------------------------------------------- finalize losses
__global__ void finalize_kernel(float* __restrict__ loss_out) {
    int s = threadIdx.x >> 5;
    int lane = threadIdx.x & 31;
    if (s >= NSCALES) return;
    int ph = (s < 13) ? c_ph[s] : 64;
    float n = (float)(B_ * ph * ph);
    float ap = g_acc[s][lane] / n;
    float H = -(ap * logf(ap + 1e-8f) + (1.f - ap) * logf(1.f - ap + 1e-8f));
#pragma unroll
    for (int o = 16; o > 0; o >>= 1) H += __shfl_xor_sync(~0u, H, o);
    if (lane == 0) {
        float ps = g_acc[s][32] / n;
        float cm = g_acc[s][33] / (n * 32.f);
        loss_out[s] = (ps - H) * (0.1f / 100.f) + 0.25f * cm;
    }
}

// ---------------------------------------------------------------- proj_out GEMM (split-N=4, 1 px/thread)
__global__ __launch_bounds__(256) void gemm_out_kernel(
        const float* __restrict__ w_out,
        const float* __restrict__ b_out,
        float* __restrict__ out) {
    __shared__ float s_wt[128 * 36];
    __shared__ float s_b[128];
    int tid = threadIdx.x;
    int kc = blockIdx.x & 3;
    int pg = blockIdx.x >> 2;
    int c0 = kc * 128;
    for (int i = tid; i < 128 * CD; i += 256) {
        int d = i >> 7, c = i & 127;
        s_wt[c * 36 + d] = w_out[d * DIMX + c0 + c];
    }
    if (tid < 128) s_b[tid] = b_out[c0 + tid];
    __syncthreads();

    int px = pg * 256 + tid;
    int b = px >> 12, pl = px & 4095;
    size_t o = (size_t)px * CD;

    unsigned long long Q[16];
#pragma unroll
    for (int k = 0; k < 8; k++) {
        float4 a = __ldg((const float4*)(g_r0 + o) + k);
        float4 r = ((const float4*)(g_r + o))[k];
        float qx = (r.x > 0.f) ? INV_SQRT32 : -INV_SQRT32;
        float qy = (r.y > 0.f) ? INV_SQRT32 : -INV_SQRT32;
        float qz = (r.z > 0.f) ? INV_SQRT32 : -INV_SQRT32;
        float qw = (r.w > 0.f) ? INV_SQRT32 : -INV_SQRT32;
        Q[2*k]   = pk2(a.x - r.x + qx, a.y - r.y + qy);
        Q[2*k+1] = pk2(a.z - r.z + qz, a.w - r.w + qw);
    }

    float* op = out + (size_t)b * (DIMX * HW) + (size_t)c0 * HW + pl;
#pragma unroll 2
    for (int c = 0; c < 128; c++) {
        const ulonglong2* wrow = (const ulonglong2*)(s_wt + c * 36);
        unsigned long long ae = 0, ao = 0;
#pragma unroll
        for (int r = 0; r < 8; r++) {
            ulonglong2 W = wrow[r];
            ae = fma2(Q[2*r],   W.x, ae);
            ao = fma2(Q[2*r+1], W.y, ao);
        }
        float lo, hi, sum;
        upk2(ae, lo, hi); sum = lo + hi;
        upk2(ao, lo, hi); sum += lo + hi;
        op[(size_t)c * HW] = sum + s_b[c];
    }
}

// ---------------------------------------------------------------- launch
extern "C" void kernel_launch(void* const* d_in, const int* in_sizes, int n_in,
                              void* d_out, int out_size) {
    const float* x     = (const float*)d_in[0];
    const float* w_in  = (const float*)d_in[1];
    const float* b_in  = (const float*)d_in[2];
    const float* w_out = (const float*)d_in[3];
    const float* b_out = (const float*)d_in[4];
    float* out = (float*)d_out;

    static const int sched[13] = {1,2,3,4,5,7,9,12,16,21,27,36,48};
    static const int SxT[7]    = {4,2,2,1,1,1,1};   // 16px x-chunks for ph 1,2,3,4,5,7,9

    gemm_in_kernel<<<1024, 256>>>(x, w_in);
    combine_kernel<<<2048, 256>>>(b_in);            // also zeroes pools + acc

    for (int s = 0; s < 12; s++) {
        int ph = sched[s];
        int ntok = B_ * ph * ph;
        int sliced = (s < 7);
        if (sliced) {
            int S = 64 / ph + 2;          // safe upper bound on region rows
            int Sx = SxT[s];
            int work = ntok * S * Sx;
            pool_small_kernel<<<(work + 7) / 8, 256>>>(s, S, Sx);
        } else {
            int blocks = (ntok + 7) / 8;
            if (blocks > 1024) blocks = 1024;
            pool_big_kernel<<<blocks, 256>>>(s);
        }
        up_kernel<<<1024, 256>>>(s, sliced);
    }
    // s = 12: pool_big then fused up+loss13
    {
        int blocks = (B_ * 48 * 48 + 7) / 8;
        if (blocks > 1024) blocks = 1024;
        pool_big_kernel<<<blocks, 256>>>(12);
    }
    up12_kernel<<<2048, 256>>>();

    if (out_size >= OUT_ELEMS + NSCALES)
        finalize_kernel<<<1, NSCALES * 32>>>(out + OUT_ELEMS);
    gemm_out_kernel<<<1024, 256>>>(w_out, b_out, out);
}

// round 15
// speedup vs baseline: 1.2079x; 1.0199x over previous
#include <cuda_runtime.h>
#include <math.h>

#define B_ 16
#define HW 4096          // 64*64
#define CD 32
#define DIMX 512
#define NSCALES 14
#define NPIX (B_*HW)                 // 65536
#define OUT_ELEMS (B_*DIMX*HW)       // 33554432

#define INV_SQRT32 0.17677669529663687f
#define ACOEF 70.710678118654755f    // 4*100/sqrt(32); p = sigmoid(-ACOEF*z)

__device__ float g_r0[NPIX*CD];      // original projection (token-major)
__device__ float g_r [NPIX*CD];      // residual
__device__ float g_part[4][NPIX*CD]; // split-K partials for proj_in
__device__ float g_pool[94720];      // pooled sums, sliced scales 0..6 only
__device__ unsigned g_bits[82720];   // sign bitmaps, scales 7..12
__device__ float g_acc[NSCALES][34]; // [0..31]=sum p, [32]=sum H, [33]=sum commit

__constant__ int c_ph[13]   = {1,2,3,4,5,7,9,12,16,21,27,36,48};
__constant__ int c_poff[7]  = {0,512,2560,7168,15360,28160,53248};    // float pools s<7
__constant__ int c_boff[13] = {0,0,0,0,0,0,0, 0,2304,6400,13456,25120,45856}; // bitmaps s>=7
#define SLICED_POOL_FLOATS 94720

// ---------------------------------------------------------------- f32x2 helpers
__device__ __forceinline__ unsigned long long pk2(float x, float y) {
    unsigned long long r;
    asm("mov.b64 %0, {%1, %2};" : "=l"(r) : "f"(x), "f"(y));
    return r;
}
__device__ __forceinline__ unsigned long long fma2(unsigned long long a,
                                                   unsigned long long b,
                                                   unsigned long long c) {
    unsigned long long d;
    asm("fma.rn.f32x2 %0, %1, %2, %3;" : "=l"(d) : "l"(a), "l"(b), "l"(c));
    return d;
}
__device__ __forceinline__ void upk2(unsigned long long v, float& lo, float& hi) {
    asm("mov.b64 {%0, %1}, %2;" : "=f"(lo), "=f"(hi) : "l"(v));
}

// ---------------------------------------------------------------- proj_in GEMM (split-K=4, 1 px/thread)
__global__ __launch_bounds__(256) void gemm_in_kernel(
        const float* __restrict__ x, const float* __restrict__ w_in) {
    __shared__ float s_w[128 * CD];
    int tid = threadIdx.x;
    int kc = blockIdx.x & 3;
    int pg = blockIdx.x >> 2;
    const float* wsrc = w_in + kc * 128 * CD;
    for (int i = tid; i < 128 * CD; i += 256) s_w[i] = wsrc[i];
    __syncthreads();

    int px = pg * 256 + tid;
    int b = px >> 12, pl = px & 4095;
    const float* xp = x + (size_t)b * (DIMX * HW) + (size_t)(kc * 128) * HW + pl;

    unsigned long long a[16];
#pragma unroll
    for (int i = 0; i < 16; i++) a[i] = 0ull;

#pragma unroll 8
    for (int c = 0; c < 128; c++) {
        float f = xp[(size_t)c * HW];
        unsigned long long X = pk2(f, f);
        const ulonglong2* row = (const ulonglong2*)(s_w + c * CD);
#pragma unroll
        for (int r = 0; r < 8; r++) {
            ulonglong2 w2 = row[r];
            a[2*r]   = fma2(X, w2.x, a[2*r]);
            a[2*r+1] = fma2(X, w2.y, a[2*r+1]);
        }
    }
    ulonglong2* o = (ulonglong2*)(g_part[kc] + (size_t)px * CD);
#pragma unroll
    for (int k = 0; k < 8; k++) {
        ulonglong2 v; v.x = a[2*k]; v.y = a[2*k+1];
        o[k] = v;
    }
}

// combine: r0 = r = ((p0+p1)+(p2+p3)) + bias ; also zeroes pools + acc
__global__ __launch_bounds__(256) void combine_kernel(const float* __restrict__ b_in) {
    int idx = blockIdx.x * 256 + threadIdx.x;
    float4 p0 = __ldg((const float4*)g_part[0] + idx);
    float4 p1 = __ldg((const float4*)g_part[1] + idx);
    float4 p2 = __ldg((const float4*)g_part[2] + idx);
    float4 p3 = __ldg((const float4*)g_part[3] + idx);
    float4 bi = __ldg((const float4*)b_in + (idx & 7));
    float4 v;
    v.x = (p0.x + p1.x) + (p2.x + p3.x) + bi.x;
    v.y = (p0.y + p1.y) + (p2.y + p3.y) + bi.y;
    v.z = (p0.z + p1.z) + (p2.z + p3.z) + bi.z;
    v.w = (p0.w + p1.w) + (p2.w + p3.w) + bi.w;
    ((float4*)g_r0)[idx] = v;
    ((float4*)g_r )[idx] = v;

    if (idx < SLICED_POOL_FLOATS) g_pool[idx] = 0.f;
    if (idx < NSCALES * 34) ((float*)g_acc)[idx] = 0.f;
}

// ---------------------------------------------------------------- per-token loss math (lane=d)
__device__ __forceinline__ void loss_token(float ir, float& pa, float& ha, float& ca) {
    float n2 = ir * ir;
#pragma unroll
    for (int o = 16; o > 0; o >>= 1) n2 += __shfl_xor_sync(~0u, n2, o);
    float z = ir / fmaxf(sqrtf(n2), 1e-12f);
    float p = 1.f / (1.f + expf(ACOEF * z));
    float H = -(p * logf(p + 1e-8f) + (1.f - p) * logf(1.f - p + 1e-8f));
    float qv = (z > 0.f) ? INV_SQRT32 : -INV_SQRT32;
    float dz = z - qv;
    pa += p; ha += H; ca += dz * dz;
}

// ---------------------------------------------------------------- pool, big scales (warp/token, fused loss, sign bitmap out)
__global__ __launch_bounds__(256) void pool_big_kernel(int s) {
    __shared__ float s_red[34];
    int tid = threadIdx.x, lane = tid & 31;
    if (tid < 34) s_red[tid] = 0.f;
    __syncthreads();

    int ph = c_ph[s], np = ph * ph, ntok = B_ * np;
    unsigned* bits = g_bits + c_boff[s];
    int gw = blockIdx.x * 8 + (tid >> 5);
    int nw = gridDim.x * 8;

    float pa = 0.f, ha = 0.f, ca = 0.f;
    for (int tok = gw; tok < ntok; tok += nw) {
        int b = tok / np, ij = tok - b * np, i = ij / ph, j = ij - i * ph;
        int sh = (i * 64) / ph, eh = ((i + 1) * 64 + ph - 1) / ph;
        int sw = (j * 64) / ph, ew = ((j + 1) * 64 + ph - 1) / ph;
        const float* rb = g_r + ((size_t)(b * HW)) * CD + lane;
        float su0 = 0.f, su1 = 0.f;
        for (int y = sh; y < eh; y++) {
            const float* row = rb + (size_t)(y * 64) * CD;
            int x = sw;
            for (; x + 2 <= ew; x += 2) {
                su0 += row[(size_t)(x+0) * CD];
                su1 += row[(size_t)(x+1) * CD];
            }
            if (x < ew) su0 += row[(size_t)x * CD];
        }
        float sum = su0 + su1;
        unsigned word = __ballot_sync(~0u, sum > 0.f);
        if (lane == 0) bits[tok] = word;
        loss_token(sum / (float)((eh - sh) * (ew - sw)), pa, ha, ca);
    }
#pragma unroll
    for (int o = 16; o > 0; o >>= 1) {
        ha += __shfl_xor_sync(~0u, ha, o);
        ca += __shfl_xor_sync(~0u, ca, o);
    }
    atomicAdd(&s_red[lane], pa);
    if (lane == 0) { atomicAdd(&s_red[32], ha); atomicAdd(&s_red[33], ca); }
    __syncthreads();
    if (tid < 34) atomicAdd(&g_acc[s][tid], s_red[tid]);
}

// ---------------------------------------------------------------- pool, small scales (row x 16px chunks, atomic, deep MLP)
__global__ __launch_bounds__(256) void pool_small_kernel(int s, int S, int Sx) {
    int tid = threadIdx.x, lane = tid & 31;
    int ph = c_ph[s], np = ph * ph, ntok = B_ * np;
    int base = c_poff[s];
    int w = blockIdx.x * 8 + (tid >> 5);
    if (w >= ntok * S * Sx) return;
    int tok = w / (S * Sx);
    int r2 = w - tok * (S * Sx);
    int sy = r2 / Sx, sx = r2 - sy * Sx;
    int b = tok / np, ij = tok - b * np, i = ij / ph, j = ij - i * ph;
    int sh = (i * 64) / ph, eh = ((i + 1) * 64 + ph - 1) / ph;
    int y = sh + sy;
    if (y >= eh) return;
    int sw = (j * 64) / ph, ew = ((j + 1) * 64 + ph - 1) / ph;
    int xs = sw + sx * 16;
    if (xs >= ew) return;
    int xe = min(ew, xs + 16);
    const float* row = g_r + ((size_t)(b * HW + y * 64)) * CD + lane;

    float s0 = 0.f, s1 = 0.f, s2 = 0.f, s3 = 0.f;
    int x = xs;
    for (; x + 8 <= xe; x += 8) {
        float a0 = row[(size_t)(x+0) * CD];
        float a1 = row[(size_t)(x+1) * CD];
        float a2 = row[(size_t)(x+2) * CD];
        float a3 = row[(size_t)(x+3) * CD];
        float a4 = row[(size_t)(x+4) * CD];
        float a5 = row[(size_t)(x+5) * CD];
        float a6 = row[(size_t)(x+6) * CD];
        float a7 = row[(size_t)(x+7) * CD];
        s0 += a0 + a4;
        s1 += a1 + a5;
        s2 += a2 + a6;
        s3 += a3 + a7;
    }
    for (; x < xe; x++) s0 += row[(size_t)x * CD];
    float sum = (s0 + s1) + (s2 + s3);
    atomicAdd(&g_pool[base + tok * CD + lane], sum);
}

// ---------------------------------------------------------------- up: r -= bilerp(sign); 16 px/warp (4 px/thread);
// fused loss for sliced scales. grid MUST be 512 blocks: 512*8 warps * 16 px = 65536
__global__ __launch_bounds__(256) void up_kernel(int s, int sliced) {
    __shared__ int s_i0[64], s_i1[64];
    __shared__ float s_f[64];
    __shared__ float s_red[34];
    int tid = threadIdx.x, lane = tid & 31;
    int ph = c_ph[s], np = ph * ph;

    if (tid < 64) {
        float src = ((float)tid + 0.5f) * (float)ph * 0.015625f - 0.5f;
        src = fminf(fmaxf(src, 0.f), (float)(ph - 1));
        int i0 = (int)src;
        s_i0[tid] = i0;
        s_i1[tid] = min(i0 + 1, ph - 1);
        s_f[tid]  = src - (float)i0;
    }
    if (tid < 34) s_red[tid] = 0.f;
    __syncthreads();

    int gw = blockIdx.x * 8 + (tid >> 5);          // 4096 warps total

    if (sliced) {
        int ntok = B_ * np;                        // <= 1296 for s<7
        if (gw < ntok) {
            const float* pool = g_pool + c_poff[s];
            int tok = gw;
            int b = tok / np, ij = tok - b * np, i = ij / ph, j = ij - i * ph;
            int ah = ((i + 1) * 64 + ph - 1) / ph - (i * 64) / ph;
            int aw = ((j + 1) * 64 + ph - 1) / ph - (j * 64) / ph;
            float ir = pool[tok * CD + lane] / (float)(ah * aw);
            float pa = 0.f, ha = 0.f, ca = 0.f;
            loss_token(ir, pa, ha, ca);
#pragma unroll
            for (int o = 16; o > 0; o >>= 1) {
                ha += __shfl_xor_sync(~0u, ha, o);
                ca += __shfl_xor_sync(~0u, ca, o);
            }
            atomicAdd(&s_red[lane], pa);
            if (lane == 0) { atomicAdd(&s_red[32], ha); atomicAdd(&s_red[33], ca); }
        }
    }

    // pixel work: lane = sub(2b)*8 + q(3b); thread handles px = gw*16 + sub + {0,4,8,12}
    int sub = lane >> 3, q = lane & 7;
    int base = gw * 16;
#pragma unroll
    for (int half = 0; half < 4; half++) {
        int px = base + sub + half * 4;
        int b = px >> 12, h = (px >> 6) & 63, w = px & 63;
        int i0 = s_i0[h], i1 = s_i1[h]; float fh = s_f[h];
        int j0 = s_i0[w], j1 = s_i1[w]; float fw = s_f[w];
        int tb = b * np;
        int t00 = tb + i0 * ph + j0, t01 = tb + i0 * ph + j1;
        int t10 = tb + i1 * ph + j0, t11 = tb + i1 * ph + j1;

        float v[4];
        if (s >= 7) {
            const unsigned* bits = g_bits + c_boff[s];
            unsigned w00 = __ldg(bits + t00), w01 = __ldg(bits + t01);
            unsigned w10 = __ldg(bits + t10), w11 = __ldg(bits + t11);
#pragma unroll
            for (int k = 0; k < 4; k++) {
                int d = 4 * q + k;
                float s00 = ((w00 >> d) & 1u) ? 1.f : -1.f;
                float s01 = ((w01 >> d) & 1u) ? 1.f : -1.f;
                float s10 = ((w10 >> d) & 1u) ? 1.f : -1.f;
                float s11 = ((w11 >> d) & 1u) ? 1.f : -1.f;
                float top = s00 + fw * (s01 - s00);
                float bot = s10 + fw * (s11 - s10);
                v[k] = INV_SQRT32 * (top + fh * (bot - top));
            }
        } else {
            const float* pool = g_pool + c_poff[s];
            float4 p00 = __ldg((const float4*)(pool + t00 * CD + 4 * q));
            float4 p01 = __ldg((const float4*)(pool + t01 * CD + 4 * q));
            float4 p10 = __ldg((const float4*)(pool + t10 * CD + 4 * q));
            float4 p11 = __ldg((const float4*)(pool + t11 * CD + 4 * q));
            const float* a00 = (const float*)&p00;
            const float* a01 = (const float*)&p01;
            const float* a10 = (const float*)&p10;
            const float* a11 = (const float*)&p11;
#pragma unroll
            for (int k = 0; k < 4; k++) {
                float s00 = a00[k] > 0.f ? 1.f : -1.f;
                float s01 = a01[k] > 0.f ? 1.f : -1.f;
                float s10 = a10[k] > 0.f ? 1.f : -1.f;
                float s11 = a11[k] > 0.f ? 1.f : -1.f;
                float top = s00 + fw * (s01 - s00);
                float bot = s10 + fw * (s11 - s10);
                v[k] = INV_SQRT32 * (top + fh * (bot - top));
            }
        }

        float4* rp = (float4*)(g_r + (size_t)px * CD + 4 * q);
        float4 rv = *rp;
        rv.x -= v[0]; rv.y -= v[1]; rv.z -= v[2]; rv.w -= v[3];
        *rp = rv;
    }

    if (sliced) {
        __syncthreads();
        if (tid < 34) atomicAdd(&g_acc[s][tid], s_red[tid]);
    }
}

// ---------------------------------------------------------------- up(12) + fused loss13; 8 px/warp (2 px/thread); grid 1024
__global__ __launch_bounds__(256) void up12_kernel() {
    __shared__ int s_i0[64], s_i1[64];
    __shared__ float s_f[64];
    __shared__ float s_13[34];
    int tid = threadIdx.x, lane = tid & 31;
    const int ph = 48, np = 48 * 48;

    if (tid < 64) {
        float src = ((float)tid + 0.5f) * 48.f * 0.015625f - 0.5f;
        src = fminf(fmaxf(src, 0.f), 47.f);
        int i0 = (int)src;
        s_i0[tid] = i0;
        s_i1[tid] = min(i0 + 1, 47);
        s_f[tid]  = src - (float)i0;
    }
    if (tid < 34) s_13[tid] = 0.f;
    __syncthreads();

    int gw = blockIdx.x * 8 + (tid >> 5);     // 8192 warps
    int sub = lane >> 3, q = lane & 7;
    const unsigned* bits = g_bits + 45856;    // scale-12 bitmap

    float pv[4] = {0.f, 0.f, 0.f, 0.f};
    float ha = 0.f, ca = 0.f;
#pragma unroll
    for (int half = 0; half < 2; half++) {
        int px = gw * 8 + sub + half * 4;
        int b = px >> 12, h = (px >> 6) & 63, w = px & 63;
        int i0 = s_i0[h], i1 = s_i1[h]; float fh = s_f[h];
        int j0 = s_i0[w], j1 = s_i1[w]; float fw = s_f[w];
        int tb = b * np;
        unsigned w00 = __ldg(bits + tb + i0 * ph + j0), w01 = __ldg(bits + tb + i0 * ph + j1);
        unsigned w10 = __ldg(bits + tb + i1 * ph + j0), w11 = __ldg(bits + tb + i1 * ph + j1);

        float4* rp = (float4*)(g_r + (size_t)px * CD + 4 * q);
        float4 rv = *rp;
        float* rvp = (float*)&rv;
#pragma unroll
        for (int k = 0; k < 4; k++) {
            int d = 4 * q + k;
            float s00 = ((w00 >> d) & 1u) ? 1.f : -1.f;
            float s01 = ((w01 >> d) & 1u) ? 1.f : -1.f;
            float s10 = ((w10 >> d) & 1u) ? 1.f : -1.f;
            float s11 = ((w11 >> d) & 1u) ? 1.f : -1.f;
            float top = s00 + fw * (s01 - s00);
            float bot = s10 + fw * (s11 - s10);
            rvp[k] -= INV_SQRT32 * (top + fh * (bot - top));
        }
        *rp = rv;

        // loss13 for this pixel (norm across 8-lane quad group)
        float n2 = rv.x*rv.x + rv.y*rv.y + rv.z*rv.z + rv.w*rv.w;
        n2 += __shfl_xor_sync(~0u, n2, 1);
        n2 += __shfl_xor_sync(~0u, n2, 2);
        n2 += __shfl_xor_sync(~0u, n2, 4);
        float inv = 1.f / fmaxf(sqrtf(n2), 1e-12f);
#pragma unroll
        for (int k = 0; k < 4; k++) {
            float z = rvp[k] * inv;
            float p = 1.f / (1.f + expf(ACOEF * z));
            ha += -(p * logf(p + 1e-8f) + (1.f - p) * logf(1.f - p + 1e-8f));
            float qv = (z > 0.f) ? INV_SQRT32 : -INV_SQRT32;
            float dz = z - qv;
            ca += dz * dz;
            pv[k] += p;
        }
    }

    atomicAdd(&s_13[4*q+0], pv[0]);
    atomicAdd(&s_13[4*q+1], pv[1]);
    atomicAdd(&s_13[4*q+2], pv[2]);
    atomicAdd(&s_13[4*q+3], pv[3]);
#pragma unroll
    for (int o = 16; o > 0; o >>= 1) {
        ha += __shfl_xor_sync(~0u, ha, o);
        ca += __shfl_xor_sync(~0u, ca, o);
    }
    if (lane == 0) { atomicAdd(&s_13[32], ha); atomicAdd(&s_13[33], ca); }

    __syncthreads();
    if (tid < 34) atomicAdd(&g_acc[13][tid], s_13[tid]);
}

// ---------------------------------------------------------------- finalize losses
__global__ void finalize_kernel(float* __restrict__ loss_out) {
    int s = threadIdx.x >> 5;
    int lane = threadIdx.x & 31;
    if (s >= NSCALES) return;
    int ph = (s < 13) ? c_ph[s] : 64;
    float n = (float)(B_ * ph * ph);
    float ap = g_acc[s][lane] / n;
    float H = -(ap * logf(ap + 1e-8f) + (1.f - ap) * logf(1.f - ap + 1e-8f));
#pragma unroll
    for (int o = 16; o > 0; o >>= 1) H += __shfl_xor_sync(~0u, H, o);
    if (lane == 0) {
        float ps = g_acc[s][32] / n;
        float cm = g_acc[s][33] / (n * 32.f);
        loss_out[s] = (ps - H) * (0.1f / 100.f) + 0.25f * cm;
    }
}

// ---------------------------------------------------------------- proj_out GEMM (split-N=4, 1 px/thread)
__global__ __launch_bounds__(256) void gemm_out_kernel(
        const float* __restrict__ w_out,
        const float* __restrict__ b_out,
        float* __restrict__ out) {
    __shared__ float s_wt[128 * 36];
    __shared__ float s_b[128];
    int tid = threadIdx.x;
    int kc = blockIdx.x & 3;
    int pg = blockIdx.x >> 2;
    int c0 = kc * 128;
    for (int i = tid; i < 128 * CD; i += 256) {
        int d = i >> 7, c = i & 127;
        s_wt[c * 36 + d] = w_out[d * DIMX + c0 + c];
    }
    if (tid < 128) s_b[tid] = b_out[c0 + tid];
    __syncthreads();

    int px = pg * 256 + tid;
    int b = px >> 12, pl = px & 4095;
    size_t o = (size_t)px * CD;

    unsigned long long Q[16];
#pragma unroll
    for (int k = 0; k < 8; k++) {
        float4 a = __ldg((const float4*)(g_r0 + o) + k);
        float4 r = ((const float4*)(g_r + o))[k];
        float qx = (r.x > 0.f) ? INV_SQRT32 : -INV_SQRT32;
        float qy = (r.y > 0.f) ? INV_SQRT32 : -INV_SQRT32;
        float qz = (r.z > 0.f) ? INV_SQRT32 : -INV_SQRT32;
        float qw = (r.w > 0.f) ? INV_SQRT32 : -INV_SQRT32;
        Q[2*k]   = pk2(a.x - r.x + qx, a.y - r.y + qy);
        Q[2*k+1] = pk2(a.z - r.z + qz, a.w - r.w + qw);
    }

    float* op = out + (size_t)b * (DIMX * HW) + (size_t)c0 * HW + pl;
#pragma unroll 2
    for (int c = 0; c < 128; c++) {
        const ulonglong2* wrow = (const ulonglong2*)(s_wt + c * 36);
        unsigned long long ae = 0, ao = 0;
#pragma unroll
        for (int r = 0; r < 8; r++) {
            ulonglong2 W = wrow[r];
            ae = fma2(Q[2*r],   W.x, ae);
            ao = fma2(Q[2*r+1], W.y, ao);
        }
        float lo, hi, sum;
        upk2(ae, lo, hi); sum = lo + hi;
        upk2(ao, lo, hi); sum += lo + hi;
        op[(size_t)c * HW] = sum + s_b[c];
    }
}

// ---------------------------------------------------------------- launch
extern "C" void kernel_launch(void* const* d_in, const int* in_sizes, int n_in,
                              void* d_out, int out_size) {
    const float* x     = (const float*)d_in[0];
    const float* w_in  = (const float*)d_in[1];
    const float* b_in  = (const float*)d_in[2];
    const float* w_out = (const float*)d_in[3];
    const float* b_out = (const float*)d_in[4];
    float* out = (float*)d_out;

    static const int sched[13] = {1,2,3,4,5,7,9,12,16,21,27,36,48};
    static const int SxT[7]    = {4,2,2,1,1,1,1};   // 16px x-chunks for ph 1,2,3,4,5,7,9

    gemm_in_kernel<<<1024, 256>>>(x, w_in);
    combine_kernel<<<2048, 256>>>(b_in);            // also zeroes pools + acc

    for (int s = 0; s < 12; s++) {
        int ph = sched[s];
        int ntok = B_ * ph * ph;
        int sliced = (s < 7);
        if (sliced) {
            int S = 64 / ph + 2;          // safe upper bound on region rows
            int Sx = SxT[s];
            int work = ntok * S * Sx;
            pool_small_kernel<<<(work + 7) / 8, 256>>>(s, S, Sx);
        } else {
            int blocks = (ntok + 7) / 8;
            if (blocks > 1024) blocks = 1024;
            pool_big_kernel<<<blocks, 256>>>(s);
        }
        up_kernel<<<512, 256>>>(s, sliced);
    }
    // s = 12: pool_big then fused up+loss13
    {
        int blocks = (B_ * 48 * 48 + 7) / 8;
        if (blocks > 1024) blocks = 1024;
        pool_big_kernel<<<blocks, 256>>>(12);
    }
    up12_kernel<<<1024, 256>>>();

    if (out_size >= OUT_ELEMS + NSCALES)
        finalize_kernel<<<1, NSCALES * 32>>>(out + OUT_ELEMS);
    gemm_out_kernel<<<1024, 256>>>(w_out, b_out, out);
}